// round 10
// baseline (speedup 1.0000x reference)
#include <cuda_runtime.h>
#include <math.h>

// HybridBasisFunction: out = wavelet(xc) + sigmoid(alpha) * spline(xc), xc = clamp(x,0,1)
//
// Piecewise-affine LUT: out = A[j] + B[j]*xc, j = floor(16*xc) in [0,16].
// (wavelet signs = binary-fraction bits of j; spline segment k=j>>2 constant
//  per bucket -> function is affine per bucket; exact vs reference.)
//
// R10: exact-6-waves. 7104 CTAs = 6 x 1184 (148 SMs x occ 8): integer wave
// count -> zero tail quantization. Chunks are SMALL (~37KB) and contiguous,
// assigned in block order so each wave's concurrent CTAs sit on adjacent
// chunks (dense instantaneous footprint — the property R8's 226KB chunks
// broke). Inner loop: batch-4 front-loaded LDG.128, .cs both streams.

#define NTHR 256
#define NBLK 7104   // 6 waves * 1184 concurrent CTAs (148 SMs * 8 @ 30 regs)

__device__ __forceinline__ float hb_eval(float v, const float* __restrict__ sA,
                                         const float* __restrict__ sB) {
    float xc = fminf(fmaxf(v, 0.0f), 1.0f);
    int j = (int)(xc * 16.0f);           // exact; j in [0,16]
    return fmaf(sB[j], xc, sA[j]);
}

__device__ __forceinline__ void hb_lut_init(const float* __restrict__ wc,
                                            const float* __restrict__ sc,
                                            const float* __restrict__ al,
                                            float* __restrict__ sA,
                                            float* __restrict__ sB) {
    if (threadIdx.x < 17) {
        int j = threadIdx.x;
        float sig = 1.0f / (1.0f + expf(-al[0]));
        float A, B;
        if (j < 16) {
            float wv = wc[0];
            wv += ((j >> 3) & 1) ? -wc[1] : wc[1];
            wv += ((j >> 2) & 1) ? -wc[2] : wc[2];
            wv += ((j >> 1) & 1) ? -wc[3] : wc[3];
            wv += ( j       & 1) ? -wc[4] : wc[4];
            int k = j >> 2;
            float c0 = sc[k], c1 = sc[k + 1];
            float d  = sig * (c1 - c0);
            A = wv + sig * c0 - (float)k * d;
            B = 4.0f * d;
        } else {
            A = wc[0] + sig * sc[4];   // xc == 1.0 exactly
            B = 0.0f;
        }
        sA[j] = A;
        sB[j] = B;
    }
    __syncthreads();
}

// Each CTA owns float4 range [start, start+len): contiguous, even split +/-1.
__global__ void __launch_bounds__(NTHR)
hybrid_basis_main(const float4* __restrict__ x4, float4* __restrict__ o4,
                  const float* __restrict__ wc, const float* __restrict__ sc,
                  const float* __restrict__ al, int base_chunk, int extra)
{
    __shared__ float sA[17];
    __shared__ float sB[17];
    hb_lut_init(wc, sc, al, sA, sB);

    int b     = blockIdx.x;
    int small = (b < extra) ? b : extra;        // +1 chunks before b
    int start = b * base_chunk + small;
    int bound = start + base_chunk + (b < extra ? 1 : 0);

    int i = start + threadIdx.x;
    // batch-4 front-loaded main loop (4 outstanding LDG.128 per thread)
    for (; i + 3 * NTHR < bound; i += 4 * NTHR) {
        float4 v0 = __ldcs(x4 + i);
        float4 v1 = __ldcs(x4 + i + NTHR);
        float4 v2 = __ldcs(x4 + i + 2 * NTHR);
        float4 v3 = __ldcs(x4 + i + 3 * NTHR);

        v0.x = hb_eval(v0.x, sA, sB); v0.y = hb_eval(v0.y, sA, sB);
        v0.z = hb_eval(v0.z, sA, sB); v0.w = hb_eval(v0.w, sA, sB);
        v1.x = hb_eval(v1.x, sA, sB); v1.y = hb_eval(v1.y, sA, sB);
        v1.z = hb_eval(v1.z, sA, sB); v1.w = hb_eval(v1.w, sA, sB);
        v2.x = hb_eval(v2.x, sA, sB); v2.y = hb_eval(v2.y, sA, sB);
        v2.z = hb_eval(v2.z, sA, sB); v2.w = hb_eval(v2.w, sA, sB);
        v3.x = hb_eval(v3.x, sA, sB); v3.y = hb_eval(v3.y, sA, sB);
        v3.z = hb_eval(v3.z, sA, sB); v3.w = hb_eval(v3.w, sA, sB);

        __stcs(o4 + i,            v0);
        __stcs(o4 + i + NTHR,     v1);
        __stcs(o4 + i + 2 * NTHR, v2);
        __stcs(o4 + i + 3 * NTHR, v3);
    }
    for (; i < bound; i += NTHR) {
        float4 v = __ldcs(x4 + i);
        v.x = hb_eval(v.x, sA, sB); v.y = hb_eval(v.y, sA, sB);
        v.z = hb_eval(v.z, sA, sB); v.w = hb_eval(v.w, sA, sB);
        __stcs(o4 + i, v);
    }
}

// Scalar tail for n % 4 != 0 (not hit for this shape).
__global__ void __launch_bounds__(NTHR)
hybrid_basis_tail(const float* __restrict__ x, float* __restrict__ out,
                  const float* __restrict__ wc, const float* __restrict__ sc,
                  const float* __restrict__ al, int start, int n)
{
    __shared__ float sA[17];
    __shared__ float sB[17];
    hb_lut_init(wc, sc, al, sA, sB);

    for (int t = start + blockIdx.x * blockDim.x + threadIdx.x; t < n;
         t += gridDim.x * blockDim.x) {
        out[t] = hb_eval(x[t], sA, sB);
    }
}

extern "C" void kernel_launch(void* const* d_in, const int* in_sizes, int n_in,
                              void* d_out, int out_size) {
    const float* x  = nullptr;
    const float* wc = nullptr;
    const float* sc = nullptr;
    const float* al = nullptr;
    long long max_sz = -1;
    int max_idx = 0;
    for (int i = 0; i < n_in; ++i) {
        if ((long long)in_sizes[i] > max_sz) { max_sz = in_sizes[i]; max_idx = i; }
    }
    for (int i = 0; i < n_in; ++i) {
        if (i == max_idx)            x  = (const float*)d_in[i];
        else if (in_sizes[i] == 5)   wc = (const float*)d_in[i];
        else if (in_sizes[i] == 8)   sc = (const float*)d_in[i];
        else if (in_sizes[i] == 1)   al = (const float*)d_in[i];
    }

    int n  = out_size;
    int n4 = n >> 2;

    if (n4 > 0) {
        int base_chunk = n4 / NBLK;
        int extra      = n4 % NBLK;
        hybrid_basis_main<<<NBLK, NTHR>>>((const float4*)x, (float4*)d_out,
                                          wc, sc, al, base_chunk, extra);
    }
    int covered = n4 << 2;
    if (covered < n) {
        int tail = n - covered;
        int tblocks = (tail + NTHR - 1) / NTHR;
        if (tblocks > 1024) tblocks = 1024;
        hybrid_basis_tail<<<tblocks, NTHR>>>(x, (float*)d_out, wc, sc, al, covered, n);
    }
}

// round 11
// speedup vs baseline: 1.0065x; 1.0065x over previous
#include <cuda_runtime.h>
#include <math.h>

// HybridBasisFunction: out = wavelet(xc) + sigmoid(alpha) * spline(xc), xc = clamp(x,0,1)
//
// Piecewise-affine reformulation: with j = floor(16*xc) (j in [0,16]),
//   - wavelet level-l sign = +1 iff bit (4-l) of j is 0   (exact: *16 is exact in fp32)
//   - spline segment k = j>>2 is constant within a bucket, lerp is affine in xc
// => out = A[j] + B[j]*xc with a 17-entry LUT in shared memory (conflict-free).
//
// FINAL CONFIG (R7, best measured; reproduced twice: 77.8/77.9us kernel,
// 6.20 TB/s, DRAM 78.2%): 8192 blocks x 256 thr x 8 float4 (32KB contiguous
// tile per CTA), batch-4 front-loaded LDG.128, evict-first (.cs) both streams.
//
// Search record (kernel us / DRAM%): grid-stride 79.3/77.4; VPT16 78.3-79.1/77.5;
// L2-pin + policy/MLP variants 78.3-78.5 (neutral); persistent-strided 83.2/73.7;
// 226KB chunks 87.5/70.5; 6-wave chunks 79.5/77.0. Conclusion: small adjacent
// tiles keep the chip's instantaneous cross-CTA footprint dense; the kernel is
// at the mixed 1:1 R/W HBM ceiling with irreducible traffic (256MB+256MB).

#define NTHR 256
#define VPT  8    // float4 per thread (2 groups of 4); 32KB contiguous tile per CTA

__device__ __forceinline__ float hb_eval(float v, const float* __restrict__ sA,
                                         const float* __restrict__ sB) {
    float xc = fminf(fmaxf(v, 0.0f), 1.0f);
    int j = (int)(xc * 16.0f);           // exact; j in [0,16]
    return fmaf(sB[j], xc, sA[j]);
}

__device__ __forceinline__ void hb_lut_init(const float* __restrict__ wc,
                                            const float* __restrict__ sc,
                                            const float* __restrict__ al,
                                            float* __restrict__ sA,
                                            float* __restrict__ sB) {
    if (threadIdx.x < 17) {
        int j = threadIdx.x;
        float sig = 1.0f / (1.0f + expf(-al[0]));
        float A, B;
        if (j < 16) {
            float wv = wc[0];
            wv += ((j >> 3) & 1) ? -wc[1] : wc[1];
            wv += ((j >> 2) & 1) ? -wc[2] : wc[2];
            wv += ((j >> 1) & 1) ? -wc[3] : wc[3];
            wv += ( j       & 1) ? -wc[4] : wc[4];
            int k = j >> 2;
            float c0 = sc[k], c1 = sc[k + 1];
            float d  = sig * (c1 - c0);
            A = wv + sig * c0 - (float)k * d;
            B = 4.0f * d;
        } else {
            A = wc[0] + sig * sc[4];   // xc == 1.0 exactly
            B = 0.0f;
        }
        sA[j] = A;
        sB[j] = B;
    }
    __syncthreads();
}

// Main kernel: each block owns a contiguous tile of NTHR*VPT float4s, exact fit.
__global__ void __launch_bounds__(NTHR)
hybrid_basis_main(const float4* __restrict__ x4, float4* __restrict__ o4,
                  const float* __restrict__ wc, const float* __restrict__ sc,
                  const float* __restrict__ al)
{
    __shared__ float sA[17];
    __shared__ float sB[17];
    hb_lut_init(wc, sc, al, sA, sB);

    int base = blockIdx.x * (NTHR * VPT) + threadIdx.x;

#pragma unroll
    for (int g = 0; g < VPT / 4; ++g) {
        int i0 = base + (g * 4 + 0) * NTHR;
        int i1 = base + (g * 4 + 1) * NTHR;
        int i2 = base + (g * 4 + 2) * NTHR;
        int i3 = base + (g * 4 + 3) * NTHR;

        float4 v0 = __ldcs(x4 + i0);
        float4 v1 = __ldcs(x4 + i1);
        float4 v2 = __ldcs(x4 + i2);
        float4 v3 = __ldcs(x4 + i3);

        v0.x = hb_eval(v0.x, sA, sB); v0.y = hb_eval(v0.y, sA, sB);
        v0.z = hb_eval(v0.z, sA, sB); v0.w = hb_eval(v0.w, sA, sB);
        v1.x = hb_eval(v1.x, sA, sB); v1.y = hb_eval(v1.y, sA, sB);
        v1.z = hb_eval(v1.z, sA, sB); v1.w = hb_eval(v1.w, sA, sB);
        v2.x = hb_eval(v2.x, sA, sB); v2.y = hb_eval(v2.y, sA, sB);
        v2.z = hb_eval(v2.z, sA, sB); v2.w = hb_eval(v2.w, sA, sB);
        v3.x = hb_eval(v3.x, sA, sB); v3.y = hb_eval(v3.y, sA, sB);
        v3.z = hb_eval(v3.z, sA, sB); v3.w = hb_eval(v3.w, sA, sB);

        __stcs(o4 + i0, v0);
        __stcs(o4 + i1, v1);
        __stcs(o4 + i2, v2);
        __stcs(o4 + i3, v3);
    }
}

// Tail kernel: scalar grid-stride over [start, n). Only launched if needed
// (not hit for the 64x4096x256 shape: 67,108,864 = 8192 * 8192 exactly).
__global__ void __launch_bounds__(NTHR)
hybrid_basis_tail(const float* __restrict__ x, float* __restrict__ out,
                  const float* __restrict__ wc, const float* __restrict__ sc,
                  const float* __restrict__ al, int start, int n)
{
    __shared__ float sA[17];
    __shared__ float sB[17];
    hb_lut_init(wc, sc, al, sA, sB);

    for (int t = start + blockIdx.x * blockDim.x + threadIdx.x; t < n;
         t += gridDim.x * blockDim.x) {
        out[t] = hb_eval(x[t], sA, sB);
    }
}

extern "C" void kernel_launch(void* const* d_in, const int* in_sizes, int n_in,
                              void* d_out, int out_size) {
    const float* x  = nullptr;
    const float* wc = nullptr;
    const float* sc = nullptr;
    const float* al = nullptr;
    long long max_sz = -1;
    int max_idx = 0;
    for (int i = 0; i < n_in; ++i) {
        if ((long long)in_sizes[i] > max_sz) { max_sz = in_sizes[i]; max_idx = i; }
    }
    for (int i = 0; i < n_in; ++i) {
        if (i == max_idx)            x  = (const float*)d_in[i];
        else if (in_sizes[i] == 5)   wc = (const float*)d_in[i];
        else if (in_sizes[i] == 8)   sc = (const float*)d_in[i];
        else if (in_sizes[i] == 1)   al = (const float*)d_in[i];
    }

    int n = out_size;
    int elems_per_block = NTHR * VPT * 4;          // 8192 elements per block
    int nblocks = n / elems_per_block;             // exact-tiled portion
    int covered = nblocks * elems_per_block;

    if (nblocks > 0) {
        hybrid_basis_main<<<nblocks, NTHR>>>((const float4*)x, (float4*)d_out, wc, sc, al);
    }
    if (covered < n) {
        int tail = n - covered;
        int tblocks = (tail + NTHR - 1) / NTHR;
        if (tblocks > 1024) tblocks = 1024;
        hybrid_basis_tail<<<tblocks, NTHR>>>(x, (float*)d_out, wc, sc, al, covered, n);
    }
}

// round 12
// speedup vs baseline: 1.0213x; 1.0147x over previous
#include <cuda_runtime.h>
#include <math.h>

// HybridBasisFunction: out = wavelet(xc) + sigmoid(alpha) * spline(xc), xc = clamp(x,0,1)
//
// Piecewise-affine reformulation: with j = floor(16*xc) (j in [0,16]),
//   - wavelet level-l sign = +1 iff bit (4-l) of j is 0   (exact: *16 is exact in fp32)
//   - spline segment k = j>>2 is constant within a bucket, lerp is affine in xc
// => out = A[j] + B[j]*xc with a 17-entry LUT in shared memory (conflict-free).
//
// R12: tile-size probe VPT 8 -> 4 (16KB contiguous tile per CTA, 16384 blocks).
// Discriminates tail-fill vs instantaneous-footprint-density models of the
// VPT16->8 win. Inner loop / cache policy identical to the converged R7 config
// (batch-4 front-loaded LDG.128, .cs both streams).

#define NTHR 256
#define VPT  4    // float4 per thread (1 group of 4); 16KB contiguous tile per CTA

__device__ __forceinline__ float hb_eval(float v, const float* __restrict__ sA,
                                         const float* __restrict__ sB) {
    float xc = fminf(fmaxf(v, 0.0f), 1.0f);
    int j = (int)(xc * 16.0f);           // exact; j in [0,16]
    return fmaf(sB[j], xc, sA[j]);
}

__device__ __forceinline__ void hb_lut_init(const float* __restrict__ wc,
                                            const float* __restrict__ sc,
                                            const float* __restrict__ al,
                                            float* __restrict__ sA,
                                            float* __restrict__ sB) {
    if (threadIdx.x < 17) {
        int j = threadIdx.x;
        float sig = 1.0f / (1.0f + expf(-al[0]));
        float A, B;
        if (j < 16) {
            float wv = wc[0];
            wv += ((j >> 3) & 1) ? -wc[1] : wc[1];
            wv += ((j >> 2) & 1) ? -wc[2] : wc[2];
            wv += ((j >> 1) & 1) ? -wc[3] : wc[3];
            wv += ( j       & 1) ? -wc[4] : wc[4];
            int k = j >> 2;
            float c0 = sc[k], c1 = sc[k + 1];
            float d  = sig * (c1 - c0);
            A = wv + sig * c0 - (float)k * d;
            B = 4.0f * d;
        } else {
            A = wc[0] + sig * sc[4];   // xc == 1.0 exactly
            B = 0.0f;
        }
        sA[j] = A;
        sB[j] = B;
    }
    __syncthreads();
}

// Main kernel: each block owns a contiguous tile of NTHR*VPT float4s, exact fit.
__global__ void __launch_bounds__(NTHR)
hybrid_basis_main(const float4* __restrict__ x4, float4* __restrict__ o4,
                  const float* __restrict__ wc, const float* __restrict__ sc,
                  const float* __restrict__ al)
{
    __shared__ float sA[17];
    __shared__ float sB[17];
    hb_lut_init(wc, sc, al, sA, sB);

    int base = blockIdx.x * (NTHR * VPT) + threadIdx.x;

    int i0 = base;
    int i1 = base + NTHR;
    int i2 = base + 2 * NTHR;
    int i3 = base + 3 * NTHR;

    float4 v0 = __ldcs(x4 + i0);
    float4 v1 = __ldcs(x4 + i1);
    float4 v2 = __ldcs(x4 + i2);
    float4 v3 = __ldcs(x4 + i3);

    v0.x = hb_eval(v0.x, sA, sB); v0.y = hb_eval(v0.y, sA, sB);
    v0.z = hb_eval(v0.z, sA, sB); v0.w = hb_eval(v0.w, sA, sB);
    v1.x = hb_eval(v1.x, sA, sB); v1.y = hb_eval(v1.y, sA, sB);
    v1.z = hb_eval(v1.z, sA, sB); v1.w = hb_eval(v1.w, sA, sB);
    v2.x = hb_eval(v2.x, sA, sB); v2.y = hb_eval(v2.y, sA, sB);
    v2.z = hb_eval(v2.z, sA, sB); v2.w = hb_eval(v2.w, sA, sB);
    v3.x = hb_eval(v3.x, sA, sB); v3.y = hb_eval(v3.y, sA, sB);
    v3.z = hb_eval(v3.z, sA, sB); v3.w = hb_eval(v3.w, sA, sB);

    __stcs(o4 + i0, v0);
    __stcs(o4 + i1, v1);
    __stcs(o4 + i2, v2);
    __stcs(o4 + i3, v3);
}

// Tail kernel: scalar grid-stride over [start, n). Only launched if needed
// (not hit for the 64x4096x256 shape: 67,108,864 = 16384 * 4096 exactly).
__global__ void __launch_bounds__(NTHR)
hybrid_basis_tail(const float* __restrict__ x, float* __restrict__ out,
                  const float* __restrict__ wc, const float* __restrict__ sc,
                  const float* __restrict__ al, int start, int n)
{
    __shared__ float sA[17];
    __shared__ float sB[17];
    hb_lut_init(wc, sc, al, sA, sB);

    for (int t = start + blockIdx.x * blockDim.x + threadIdx.x; t < n;
         t += gridDim.x * blockDim.x) {
        out[t] = hb_eval(x[t], sA, sB);
    }
}

extern "C" void kernel_launch(void* const* d_in, const int* in_sizes, int n_in,
                              void* d_out, int out_size) {
    const float* x  = nullptr;
    const float* wc = nullptr;
    const float* sc = nullptr;
    const float* al = nullptr;
    long long max_sz = -1;
    int max_idx = 0;
    for (int i = 0; i < n_in; ++i) {
        if ((long long)in_sizes[i] > max_sz) { max_sz = in_sizes[i]; max_idx = i; }
    }
    for (int i = 0; i < n_in; ++i) {
        if (i == max_idx)            x  = (const float*)d_in[i];
        else if (in_sizes[i] == 5)   wc = (const float*)d_in[i];
        else if (in_sizes[i] == 8)   sc = (const float*)d_in[i];
        else if (in_sizes[i] == 1)   al = (const float*)d_in[i];
    }

    int n = out_size;
    int elems_per_block = NTHR * VPT * 4;          // 4096 elements per block
    int nblocks = n / elems_per_block;             // exact-tiled portion
    int covered = nblocks * elems_per_block;

    if (nblocks > 0) {
        hybrid_basis_main<<<nblocks, NTHR>>>((const float4*)x, (float4*)d_out, wc, sc, al);
    }
    if (covered < n) {
        int tail = n - covered;
        int tblocks = (tail + NTHR - 1) / NTHR;
        if (tblocks > 1024) tblocks = 1024;
        hybrid_basis_tail<<<tblocks, NTHR>>>(x, (float*)d_out, wc, sc, al, covered, n);
    }
}

// round 13
// speedup vs baseline: 1.0249x; 1.0035x over previous
#include <cuda_runtime.h>
#include <math.h>

// HybridBasisFunction: out = wavelet(xc) + sigmoid(alpha) * spline(xc), xc = clamp(x,0,1)
//
// Piecewise-affine reformulation: with j = floor(16*xc) (j in [0,16]),
//   - wavelet level-l sign = +1 iff bit (4-l) of j is 0   (exact: *16 is exact in fp32)
//   - spline segment k = j>>2 is constant within a bucket, lerp is affine in xc
// => out = A[j] + B[j]*xc with a 17-entry LUT in shared memory (conflict-free).
//
// R13: tile-size axis continued (monotone win so far: 64KB 79.1us -> 32KB 77.8
// -> 16KB 76.8; DRAM% 77.5 -> 78.2 -> 79.2). Now 8KB tiles via NTHR 256 -> 128
// with VPT=4 unchanged, preserving the batch-4 front-loaded LDG.128 pattern.
// 32768 blocks x 128 thr x 4 float4 = exact fit. Denser instantaneous
// cross-CTA footprint (~19MB active span).

#define NTHR 128
#define VPT  4    // float4 per thread (1 group of 4); 8KB contiguous tile per CTA

__device__ __forceinline__ float hb_eval(float v, const float* __restrict__ sA,
                                         const float* __restrict__ sB) {
    float xc = fminf(fmaxf(v, 0.0f), 1.0f);
    int j = (int)(xc * 16.0f);           // exact; j in [0,16]
    return fmaf(sB[j], xc, sA[j]);
}

__device__ __forceinline__ void hb_lut_init(const float* __restrict__ wc,
                                            const float* __restrict__ sc,
                                            const float* __restrict__ al,
                                            float* __restrict__ sA,
                                            float* __restrict__ sB) {
    if (threadIdx.x < 17) {
        int j = threadIdx.x;
        float sig = 1.0f / (1.0f + expf(-al[0]));
        float A, B;
        if (j < 16) {
            float wv = wc[0];
            wv += ((j >> 3) & 1) ? -wc[1] : wc[1];
            wv += ((j >> 2) & 1) ? -wc[2] : wc[2];
            wv += ((j >> 1) & 1) ? -wc[3] : wc[3];
            wv += ( j       & 1) ? -wc[4] : wc[4];
            int k = j >> 2;
            float c0 = sc[k], c1 = sc[k + 1];
            float d  = sig * (c1 - c0);
            A = wv + sig * c0 - (float)k * d;
            B = 4.0f * d;
        } else {
            A = wc[0] + sig * sc[4];   // xc == 1.0 exactly
            B = 0.0f;
        }
        sA[j] = A;
        sB[j] = B;
    }
    __syncthreads();
}

// Main kernel: each block owns a contiguous tile of NTHR*VPT float4s, exact fit.
__global__ void __launch_bounds__(NTHR)
hybrid_basis_main(const float4* __restrict__ x4, float4* __restrict__ o4,
                  const float* __restrict__ wc, const float* __restrict__ sc,
                  const float* __restrict__ al)
{
    __shared__ float sA[17];
    __shared__ float sB[17];
    hb_lut_init(wc, sc, al, sA, sB);

    int base = blockIdx.x * (NTHR * VPT) + threadIdx.x;

    int i0 = base;
    int i1 = base + NTHR;
    int i2 = base + 2 * NTHR;
    int i3 = base + 3 * NTHR;

    float4 v0 = __ldcs(x4 + i0);
    float4 v1 = __ldcs(x4 + i1);
    float4 v2 = __ldcs(x4 + i2);
    float4 v3 = __ldcs(x4 + i3);

    v0.x = hb_eval(v0.x, sA, sB); v0.y = hb_eval(v0.y, sA, sB);
    v0.z = hb_eval(v0.z, sA, sB); v0.w = hb_eval(v0.w, sA, sB);
    v1.x = hb_eval(v1.x, sA, sB); v1.y = hb_eval(v1.y, sA, sB);
    v1.z = hb_eval(v1.z, sA, sB); v1.w = hb_eval(v1.w, sA, sB);
    v2.x = hb_eval(v2.x, sA, sB); v2.y = hb_eval(v2.y, sA, sB);
    v2.z = hb_eval(v2.z, sA, sB); v2.w = hb_eval(v2.w, sA, sB);
    v3.x = hb_eval(v3.x, sA, sB); v3.y = hb_eval(v3.y, sA, sB);
    v3.z = hb_eval(v3.z, sA, sB); v3.w = hb_eval(v3.w, sA, sB);

    __stcs(o4 + i0, v0);
    __stcs(o4 + i1, v1);
    __stcs(o4 + i2, v2);
    __stcs(o4 + i3, v3);
}

// Tail kernel: scalar grid-stride over [start, n). Only launched if needed
// (not hit for the 64x4096x256 shape: 67,108,864 = 32768 * 2048 exactly).
__global__ void __launch_bounds__(NTHR)
hybrid_basis_tail(const float* __restrict__ x, float* __restrict__ out,
                  const float* __restrict__ wc, const float* __restrict__ sc,
                  const float* __restrict__ al, int start, int n)
{
    __shared__ float sA[17];
    __shared__ float sB[17];
    hb_lut_init(wc, sc, al, sA, sB);

    for (int t = start + blockIdx.x * blockDim.x + threadIdx.x; t < n;
         t += gridDim.x * blockDim.x) {
        out[t] = hb_eval(x[t], sA, sB);
    }
}

extern "C" void kernel_launch(void* const* d_in, const int* in_sizes, int n_in,
                              void* d_out, int out_size) {
    const float* x  = nullptr;
    const float* wc = nullptr;
    const float* sc = nullptr;
    const float* al = nullptr;
    long long max_sz = -1;
    int max_idx = 0;
    for (int i = 0; i < n_in; ++i) {
        if ((long long)in_sizes[i] > max_sz) { max_sz = in_sizes[i]; max_idx = i; }
    }
    for (int i = 0; i < n_in; ++i) {
        if (i == max_idx)            x  = (const float*)d_in[i];
        else if (in_sizes[i] == 5)   wc = (const float*)d_in[i];
        else if (in_sizes[i] == 8)   sc = (const float*)d_in[i];
        else if (in_sizes[i] == 1)   al = (const float*)d_in[i];
    }

    int n = out_size;
    int elems_per_block = NTHR * VPT * 4;          // 2048 elements per block
    int nblocks = n / elems_per_block;             // exact-tiled portion
    int covered = nblocks * elems_per_block;

    if (nblocks > 0) {
        hybrid_basis_main<<<nblocks, NTHR>>>((const float4*)x, (float4*)d_out, wc, sc, al);
    }
    if (covered < n) {
        int tail = n - covered;
        int tblocks = (tail + NTHR - 1) / NTHR;
        if (tblocks > 1024) tblocks = 1024;
        hybrid_basis_tail<<<tblocks, NTHR>>>(x, (float*)d_out, wc, sc, al, covered, n);
    }
}